// round 6
// baseline (speedup 1.0000x reference)
#include <cuda_runtime.h>

// SampledPairwiseMarginRankingLoss:
//   loss = sum_{p<P, s<S} relu(MARGIN - scores[p] + scores[P + neg_idx[p*S+s]]) / (P*S)
// Positives are statically indices [0,P): the target array (d_in[1]) is never needed.
//
// R6: 2-launch chunked gather (L2 phase coherence, from R5) +
//  - group-of-20 tiling: 20 pairs = 5 int4 idx loads + ONE float4 pos load
//    (npairs is exactly divisible by 20, p advances by 4 per group)
//  - branch-free clamped gathers: out-of-chunk idx clamps to a resident
//    warp-uniform address (broadcast L1 hit) and the contribution selects to 0.
//    All 20 gathers issue unconditionally -> front-batched, MLP ~20/warp.

#define MARGIN   1.0f
#define NTHREADS 256
#define NBLOCKS  1216   /* 152 SMs x 8 blocks */
#define NCHUNKS  2

__device__ float        g_partials[NCHUNKS][NBLOCKS];
__device__ unsigned int g_done_count = 0;

__device__ __forceinline__ unsigned long long make_evict_last_policy() {
    unsigned long long pol;
    asm("createpolicy.fractional.L2::evict_last.b64 %0, 1.0;" : "=l"(pol));
    return pol;
}

__device__ __forceinline__ float ldg_hint(const float* p, unsigned long long pol) {
    float v;
    asm volatile("ld.global.nc.L2::cache_hint.f32 %0, [%1], %2;"
                 : "=f"(v) : "l"(p), "l"(pol));
    return v;
}

__global__ void __launch_bounds__(NTHREADS)
pair_loss_chunk_kernel(const float* __restrict__ scores,
                       const int*   __restrict__ neg_idx,
                       float* __restrict__ out,
                       int npairs, int P,
                       int lo, int hi,            // chunk bounds (negative index space)
                       int slot, int do_reduce,
                       float inv_count)
{
    const float* __restrict__ negbase = scores + P;
    const unsigned long long pol = make_evict_last_policy();
    float acc = 0.0f;

    const int tid     = blockIdx.x * blockDim.x + threadIdx.x;
    const int stride  = gridDim.x * blockDim.x;
    const int ngroups = npairs / 20;               // exact for this problem

    const int4*   __restrict__ nidx4 = (const int4*)neg_idx;
    const float4* __restrict__ pos4  = (const float4*)scores;

    for (int g = tid; g < ngroups; g += stride) {
        // 5 int4 index loads covering pairs [20g, 20g+20)
        int4 i0 = __ldcs(nidx4 + 5 * g + 0);
        int4 i1 = __ldcs(nidx4 + 5 * g + 1);
        int4 i2 = __ldcs(nidx4 + 5 * g + 2);
        int4 i3 = __ldcs(nidx4 + 5 * g + 3);
        int4 i4 = __ldcs(nidx4 + 5 * g + 4);
        // one float4 positive load: p = 4g .. 4g+3 (pair k uses pos[k/5])
        float4 pv = __ldg(pos4 + g);

        int   idx[20] = { i0.x, i0.y, i0.z, i0.w, i1.x,
                          i1.y, i1.z, i1.w, i2.x, i2.y,
                          i2.z, i2.w, i3.x, i3.y, i3.z,
                          i3.w, i4.x, i4.y, i4.z, i4.w };
        float pos[4]  = { pv.x, pv.y, pv.z, pv.w };

        float neg[20];
        bool  ok[20];
        #pragma unroll
        for (int k = 0; k < 20; ++k) {
            ok[k] = (idx[k] >= lo) && (idx[k] < hi);
            int safe = ok[k] ? idx[k] : lo;        // resident broadcast addr
            neg[k] = ldg_hint(negbase + safe, pol);
        }

        #pragma unroll
        for (int k = 0; k < 20; ++k) {
            float term = fmaxf(MARGIN - pos[k / 5] + neg[k], 0.0f);
            acc += ok[k] ? term : 0.0f;
        }
    }

    // generic scalar tail (empty for this problem's sizes)
    for (int q = ngroups * 20 + tid; q < npairs; q += stride) {
        int idx = __ldcs(neg_idx + q);
        if (idx >= lo && idx < hi) {
            float pos = __ldg(scores + q / 5);
            float neg = ldg_hint(negbase + idx, pol);
            acc += fmaxf(MARGIN - pos + neg, 0.0f);
        }
    }

    // intra-block reduction
    #pragma unroll
    for (int off = 16; off > 0; off >>= 1)
        acc += __shfl_xor_sync(0xffffffffu, acc, off);

    __shared__ float warp_sums[NTHREADS / 32];
    __shared__ bool  is_last;
    const int lane = threadIdx.x & 31;
    const int wid  = threadIdx.x >> 5;
    if (lane == 0) warp_sums[wid] = acc;
    __syncthreads();

    if (wid == 0) {
        float bsum = (lane < NTHREADS / 32) ? warp_sums[lane] : 0.0f;
        #pragma unroll
        for (int off = 4; off > 0; off >>= 1)
            bsum += __shfl_xor_sync(0xffffffffu, bsum, off);
        if (lane == 0) {
            g_partials[slot][blockIdx.x] = bsum;
            if (do_reduce) {
                __threadfence();
                unsigned prev = atomicAdd(&g_done_count, 1u);
                is_last = (prev == gridDim.x - 1);
            } else {
                is_last = false;
            }
        }
    }
    __syncthreads();

    if (!is_last) return;

    // last block of final launch: deterministic double-precision reduce
    double dacc = 0.0;
    for (int i = threadIdx.x; i < NCHUNKS * NBLOCKS; i += NTHREADS)
        dacc += (double)(&g_partials[0][0])[i];

    #pragma unroll
    for (int off = 16; off > 0; off >>= 1)
        dacc += __shfl_xor_sync(0xffffffffu, dacc, off);

    __shared__ double dwarp[NTHREADS / 32];
    if (lane == 0) dwarp[wid] = dacc;
    __syncthreads();

    if (wid == 0) {
        double v = (lane < NTHREADS / 32) ? dwarp[lane] : 0.0;
        #pragma unroll
        for (int off = 4; off > 0; off >>= 1)
            v += __shfl_xor_sync(0xffffffffu, v, off);
        if (lane == 0) {
            out[0] = (float)(v * (double)inv_count);
            g_done_count = 0;   // reset for next graph replay
        }
    }
}

extern "C" void kernel_launch(void* const* d_in, const int* in_sizes, int n_in,
                              void* d_out, int out_size)
{
    const float* scores  = (const float*)d_in[0];
    // d_in[1] = target (unused: positives are statically indices [0,P))
    const int*   neg_idx = (const int*)d_in[2];

    int N      = in_sizes[0];          // 33,554,432
    int npairs = in_sizes[2];          // P * S = 20,971,520
    int P      = npairs / 5;           // 4,194,304
    int nneg   = N - P;                // 29,360,128
    int chunk  = (nneg + NCHUNKS - 1) / NCHUNKS;
    float invc = 1.0f / (float)npairs;

    for (int c = 0; c < NCHUNKS; ++c) {
        int lo = c * chunk;
        int hi = lo + chunk;
        pair_loss_chunk_kernel<<<NBLOCKS, NTHREADS>>>(
            scores, neg_idx, (float*)d_out, npairs, P,
            lo, hi, c, (c == NCHUNKS - 1) ? 1 : 0, invc);
    }
}

// round 7
// speedup vs baseline: 1.1452x; 1.1452x over previous
#include <cuda_runtime.h>

// SampledPairwiseMarginRankingLoss:
//   loss = sum_{p<P, s<S} relu(MARGIN - scores[p] + scores[P + neg_idx[p*S+s]]) / (P*S)
// Positives are statically indices [0,P): the target array (d_in[1]) is never needed.
//
// R7 = R5 (2-launch chunked gather for L2 phase coherence, fully coalesced
// index stream) + branch-free clamped gathers (all 8 gathers per iteration
// issue unconditionally; out-of-chunk lanes clamp to a resident warp-uniform
// address and select to 0) + launch_bounds(256,6) so ptxas keeps the loads
// in flight instead of recycling registers.

#define MARGIN   1.0f
#define NTHREADS 256
#define NBLOCKS  1216   /* 152 SMs x 8 launched; ~6 resident at 42 regs */
#define NCHUNKS  2

__device__ float        g_partials[NCHUNKS][NBLOCKS];
__device__ unsigned int g_done_count = 0;

__device__ __forceinline__ unsigned long long make_evict_last_policy() {
    unsigned long long pol;
    asm("createpolicy.fractional.L2::evict_last.b64 %0, 1.0;" : "=l"(pol));
    return pol;
}

__device__ __forceinline__ float ldg_hint(const float* p, unsigned long long pol) {
    float v;
    asm volatile("ld.global.nc.L2::cache_hint.f32 %0, [%1], %2;"
                 : "=f"(v) : "l"(p), "l"(pol));
    return v;
}

__global__ void __launch_bounds__(NTHREADS, 6)
pair_loss_chunk_kernel(const float* __restrict__ scores,
                       const int*   __restrict__ neg_idx,
                       float* __restrict__ out,
                       int npairs, int P,
                       int lo, int hi,            // chunk bounds (negative index space)
                       int slot, int do_reduce,
                       float inv_count)
{
    const float* __restrict__ negbase = scores + P;
    const unsigned long long pol = make_evict_last_policy();
    float acc = 0.0f;

    const int tid    = blockIdx.x * blockDim.x + threadIdx.x;
    const int stride = gridDim.x * blockDim.x;
    const int nvec   = npairs >> 2;

    const int4* __restrict__ nidx4 = (const int4*)neg_idx;

    for (int v = tid; v < nvec; v += 2 * stride) {
        const int v2 = v + stride;
        int4 ia = __ldcs(nidx4 + v);                       // coalesced
        int4 ib = (v2 < nvec) ? __ldcs(nidx4 + v2)
                              : make_int4(lo, lo, lo, lo); // resident dummy

        const int qa = v  << 2;
        const int qb = v2 << 2;
        const bool bvalid = (v2 < nvec);

        int idx[8]  = { ia.x, ia.y, ia.z, ia.w, ib.x, ib.y, ib.z, ib.w };
        int pidx[8] = { qa/5, (qa+1)/5, (qa+2)/5, (qa+3)/5,
                        qb/5, (qb+1)/5, (qb+2)/5, (qb+3)/5 };

        bool  ok[8];
        float neg[8], pos[8];
        #pragma unroll
        for (int k = 0; k < 8; ++k) {
            ok[k] = (idx[k] >= lo) && (idx[k] < hi) && (k < 4 || bvalid);
            int safe = ok[k] ? idx[k] : lo;                // broadcast L1 hit
            neg[k] = ldg_hint(negbase + safe, pol);
            pos[k] = __ldg(scores + pidx[k]);              // L1 broadcast
        }

        #pragma unroll
        for (int k = 0; k < 8; ++k) {
            float term = fmaxf(MARGIN - pos[k] + neg[k], 0.0f);
            acc += ok[k] ? term : 0.0f;
        }
    }

    // scalar tail (npairs not a multiple of 4)
    for (int q = (nvec << 2) + tid; q < npairs; q += stride) {
        int idx = __ldcs(neg_idx + q);
        if (idx >= lo && idx < hi) {
            float pos = __ldg(scores + q / 5);
            float neg = ldg_hint(negbase + idx, pol);
            acc += fmaxf(MARGIN - pos + neg, 0.0f);
        }
    }

    // intra-block reduction
    #pragma unroll
    for (int off = 16; off > 0; off >>= 1)
        acc += __shfl_xor_sync(0xffffffffu, acc, off);

    __shared__ float warp_sums[NTHREADS / 32];
    __shared__ bool  is_last;
    const int lane = threadIdx.x & 31;
    const int wid  = threadIdx.x >> 5;
    if (lane == 0) warp_sums[wid] = acc;
    __syncthreads();

    if (wid == 0) {
        float bsum = (lane < NTHREADS / 32) ? warp_sums[lane] : 0.0f;
        #pragma unroll
        for (int off = 4; off > 0; off >>= 1)
            bsum += __shfl_xor_sync(0xffffffffu, bsum, off);
        if (lane == 0) {
            g_partials[slot][blockIdx.x] = bsum;
            if (do_reduce) {
                __threadfence();
                unsigned prev = atomicAdd(&g_done_count, 1u);
                is_last = (prev == gridDim.x - 1);
            } else {
                is_last = false;
            }
        }
    }
    __syncthreads();

    if (!is_last) return;

    // last block of final launch: deterministic double-precision reduce
    double dacc = 0.0;
    for (int i = threadIdx.x; i < NCHUNKS * NBLOCKS; i += NTHREADS)
        dacc += (double)(&g_partials[0][0])[i];

    #pragma unroll
    for (int off = 16; off > 0; off >>= 1)
        dacc += __shfl_xor_sync(0xffffffffu, dacc, off);

    __shared__ double dwarp[NTHREADS / 32];
    if (lane == 0) dwarp[wid] = dacc;
    __syncthreads();

    if (wid == 0) {
        double v = (lane < NTHREADS / 32) ? dwarp[lane] : 0.0;
        #pragma unroll
        for (int off = 4; off > 0; off >>= 1)
            v += __shfl_xor_sync(0xffffffffu, v, off);
        if (lane == 0) {
            out[0] = (float)(v * (double)inv_count);
            g_done_count = 0;   // reset for next graph replay
        }
    }
}

extern "C" void kernel_launch(void* const* d_in, const int* in_sizes, int n_in,
                              void* d_out, int out_size)
{
    const float* scores  = (const float*)d_in[0];
    // d_in[1] = target (unused: positives are statically indices [0,P))
    const int*   neg_idx = (const int*)d_in[2];

    int N      = in_sizes[0];          // 33,554,432
    int npairs = in_sizes[2];          // P * S = 20,971,520
    int P      = npairs / 5;           // 4,194,304
    int nneg   = N - P;                // 29,360,128
    int chunk  = (nneg + NCHUNKS - 1) / NCHUNKS;
    float invc = 1.0f / (float)npairs;

    for (int c = 0; c < NCHUNKS; ++c) {
        int lo = c * chunk;
        int hi = lo + chunk;
        pair_loss_chunk_kernel<<<NBLOCKS, NTHREADS>>>(
            scores, neg_idx, (float*)d_out, npairs, P,
            lo, hi, c, (c == NCHUNKS - 1) ? 1 : 0, invc);
    }
}